// round 1
// baseline (speedup 1.0000x reference)
#include <cuda_runtime.h>
#include <math.h>

// Fixed problem shape per setup_inputs (B=8192, P=16) but coded generically.
#define MAXB 8192

// Scratch (allocations are forbidden; use device globals).
__device__ float2 g_de[MAXB];                 // {distance, energy} per row
__device__ double g_sum;                      // masked pair-loss sum
__device__ unsigned long long g_cnt;          // mask count

// ---------------------------------------------------------------------------
// Kernel 1: distances + pack (d_i, e_i), and zero the accumulators.
// ---------------------------------------------------------------------------
__global__ void prep_kernel(const float* __restrict__ energies,
                            const float* __restrict__ pv,
                            const float* __restrict__ pt,
                            int B, int P) {
    if (blockIdx.x == 0 && threadIdx.x == 0) {
        g_sum = 0.0;
        g_cnt = 0ull;
    }
    int i = blockIdx.x * blockDim.x + threadIdx.x;
    if (i < B) {
        float s = 0.0f;
        #pragma unroll 16
        for (int p = 0; p < P; p++) {
            float df = pv[i * P + p] - pt[p];
            s = fmaf(df, df, s);
        }
        g_de[i] = make_float2(sqrtf(s), energies[i]);
    }
}

// ---------------------------------------------------------------------------
// Kernel 2: O(B^2) pairwise masked loss.
// Grid: (B/IT, B/JT). Each block: IT threads (one i each), j-tile of JT in
// shared memory (broadcast reads — conflict-free).
// ---------------------------------------------------------------------------
constexpr int IT = 256;
constexpr int JT = 1024;

__global__ __launch_bounds__(IT) void pair_kernel(int B) {
    __shared__ float2 tile[JT];

    int i = blockIdx.x * IT + threadIdx.x;
    float di = 1e30f;   // invalid i: mask always false (1e30 < anything real is false)
    float ei = 0.0f;
    if (i < B) {
        float2 v = g_de[i];
        di = v.x;
        ei = v.y;
    }

    int j0 = blockIdx.y * JT;
    #pragma unroll 4
    for (int j = threadIdx.x; j < JT; j += IT) {
        int gj = j0 + j;
        tile[j] = (gj < B) ? g_de[gj] : make_float2(-1e30f, 0.0f); // dj=-inf -> mask false
    }
    __syncthreads();

    float eplus = ei + 1.0f;   // hoist the +MARGIN
    float acc = 0.0f;
    unsigned int cnt = 0;

    #pragma unroll 8
    for (int j = 0; j < JT; j++) {
        float2 t = tile[j];                       // LDS.64 broadcast
        float v = fmaxf(eplus - t.y, 0.0f);       // relu(e_i - e_j + 1)
        bool m = di < t.x;                        // strict: i==j auto-excluded
        acc += m ? v : 0.0f;
        cnt += m ? 1u : 0u;
    }

    // Warp reduction
    #pragma unroll
    for (int o = 16; o > 0; o >>= 1) {
        acc += __shfl_down_sync(0xFFFFFFFFu, acc, o);
        cnt += __shfl_down_sync(0xFFFFFFFFu, cnt, o);
    }

    __shared__ float  ssum[IT / 32];
    __shared__ unsigned int scnt[IT / 32];
    int w = threadIdx.x >> 5;
    int l = threadIdx.x & 31;
    if (l == 0) { ssum[w] = acc; scnt[w] = cnt; }
    __syncthreads();

    if (threadIdx.x == 0) {
        float a = 0.0f;
        unsigned int c = 0;
        #pragma unroll
        for (int k = 0; k < IT / 32; k++) { a += ssum[k]; c += scnt[k]; }
        atomicAdd(&g_sum, (double)a);
        atomicAdd(&g_cnt, (unsigned long long)c);
    }
}

// ---------------------------------------------------------------------------
// Kernel 3: final divide.
// ---------------------------------------------------------------------------
__global__ void final_kernel(float* __restrict__ out) {
    double c = (double)g_cnt;
    if (c < 1.0) c = 1.0;
    out[0] = (float)(g_sum / c);
}

// ---------------------------------------------------------------------------
extern "C" void kernel_launch(void* const* d_in, const int* in_sizes, int n_in,
                              void* d_out, int out_size) {
    const float* energies = (const float*)d_in[0];   // (B, 1)
    const float* pv       = (const float*)d_in[1];   // (B, P)
    const float* pt       = (const float*)d_in[2];   // (P,)
    float* out            = (float*)d_out;

    int B = in_sizes[0];                 // B*1
    int P = in_sizes[2];                 // P
    if (B > MAXB) B = MAXB;

    int pb = (B + 255) / 256;
    prep_kernel<<<pb, 256>>>(energies, pv, pt, B, P);

    dim3 grid((B + IT - 1) / IT, (B + JT - 1) / JT);
    pair_kernel<<<grid, IT>>>(B);

    final_kernel<<<1, 1>>>(out);
}

// round 2
// speedup vs baseline: 1.8243x; 1.8243x over previous
#include <cuda_runtime.h>
#include <math.h>

#define MAXB 16384

// Scratch (no allocations allowed) — {d^2, e} per row.
__device__ float2 g_de[MAXB];
__device__ double g_sum;

// ---------------------------------------------------------------------------
// Kernel 1: squared distances + pack {d2, e}; zero the sum accumulator.
// Fast path for P==16 uses 4 threads/row with float4 loads (MLP, coalesced).
// ---------------------------------------------------------------------------
__global__ void prep_kernel(const float* __restrict__ energies,
                            const float* __restrict__ pv,
                            const float* __restrict__ pt,
                            int B, int P) {
    if (blockIdx.x == 0 && threadIdx.x == 0) g_sum = 0.0;

    int t = blockIdx.x * blockDim.x + threadIdx.x;
    if (P == 16) {
        int row = t >> 2;
        int q   = t & 3;
        if (row < B) {
            const float4* pv4 = (const float4*)pv;
            const float4* pt4 = (const float4*)pt;
            float4 v = pv4[row * 4 + q];
            float4 w = pt4[q];
            float a = v.x - w.x, b = v.y - w.y, c = v.z - w.z, d = v.w - w.w;
            float s = fmaf(a, a, fmaf(b, b, fmaf(c, c, d * d)));
            s += __shfl_xor_sync(0xFFFFFFFFu, s, 1);
            s += __shfl_xor_sync(0xFFFFFFFFu, s, 2);
            if (q == 0) g_de[row] = make_float2(s, energies[row]);
        }
    } else {
        // generic fallback: one thread per row
        if (t < B) {
            float s = 0.0f;
            for (int p = 0; p < P; p++) {
                float df = pv[t * P + p] - pt[p];
                s = fmaf(df, df, s);
            }
            g_de[t] = make_float2(s, energies[t]);
        }
    }
}

// ---------------------------------------------------------------------------
// Kernel 2: upper-triangle tiled pairwise loss with direction-select.
// For each unordered pair {i,j}: exactly one of (i,j)/(j,i) is masked-in
// (ties negligible), so add relu over the direction with the smaller d^2.
// Tiles: TILE x TILE; blocks enumerate ti <= tj (T*(T+1)/2 blocks).
// ---------------------------------------------------------------------------
constexpr int TILE = 256;

__global__ __launch_bounds__(TILE) void pair_kernel(int B, int T) {
    // --- triangle decode: prefix(ti) = ti*T - ti*(ti-1)/2 ---
    int bid = blockIdx.x;
    float tf = 2.0f * T + 1.0f;
    int ti = (int)floorf((tf - sqrtf(tf * tf - 8.0f * (float)bid)) * 0.5f);
    if (ti < 0) ti = 0;
    if (ti > T - 1) ti = T - 1;
    while (ti > 0 && (ti * T - ti * (ti - 1) / 2) > bid) ti--;
    while (((ti + 1) * T - (ti + 1) * ti / 2) <= bid) ti++;
    int tj = ti + (bid - (ti * T - ti * (ti - 1) / 2));

    __shared__ float2 tile[TILE];

    const float NANF = __int_as_float(0x7FC00000);

    // load j-tile (NaN energy pad -> relu(NaN)=fmaxf(NaN,0)=0 contribution)
    {
        int gj = tj * TILE + threadIdx.x;
        float2 v = (gj < B) ? g_de[gj] : make_float2(0.0f, NANF);
        tile[threadIdx.x] = v;
    }

    // load this thread's i row
    int ig = ti * TILE + threadIdx.x;
    float di = 0.0f, ai, bi;
    if (ig < B) {
        float2 v = g_de[ig];
        di = v.x;
        ai = v.y + 1.0f;    // e_i + 1  (s1 = ai - e_j)
        bi = 1.0f - v.y;    // 1 - e_i  (s2 = bi + e_j)
    } else {
        ai = NANF;          // invalid i: both directions NaN -> relu = 0
        bi = NANF;
    }
    __syncthreads();

    float acc0 = 0.0f, acc1 = 0.0f;

    if (ti != tj) {
        // off-diagonal tile: every (i, j) is a distinct unordered pair
        #pragma unroll 8
        for (int j = 0; j < TILE; j += 2) {
            float2 t0 = tile[j];
            float2 t1 = tile[j + 1];
            float v0 = (di < t0.x) ? (ai - t0.y) : (bi + t0.y);
            float v1 = (di < t1.x) ? (ai - t1.y) : (bi + t1.y);
            acc0 += fmaxf(v0, 0.0f);
            acc1 += fmaxf(v1, 0.0f);
        }
    } else {
        // diagonal tile: only j > i (strict) to visit each pair once
        int il = threadIdx.x;
        #pragma unroll 8
        for (int j = 0; j < TILE; j++) {
            float2 t = tile[j];
            float v = (di < t.x) ? (ai - t.y) : (bi + t.y);
            float r = fmaxf(v, 0.0f);
            if (j > il) acc0 += r;
        }
    }

    float acc = acc0 + acc1;

    // warp + block reduction, then one double atomic per block
    #pragma unroll
    for (int o = 16; o > 0; o >>= 1)
        acc += __shfl_down_sync(0xFFFFFFFFu, acc, o);

    __shared__ float ssum[TILE / 32];
    int w = threadIdx.x >> 5, l = threadIdx.x & 31;
    if (l == 0) ssum[w] = acc;
    __syncthreads();
    if (threadIdx.x == 0) {
        float a = 0.0f;
        #pragma unroll
        for (int k = 0; k < TILE / 32; k++) a += ssum[k];
        atomicAdd(&g_sum, (double)a);
    }
}

// ---------------------------------------------------------------------------
// Kernel 3: final divide (count = B*(B-1)/2, computed host-side).
// ---------------------------------------------------------------------------
__global__ void final_kernel(float* __restrict__ out, double cnt) {
    out[0] = (float)(g_sum / cnt);
}

// ---------------------------------------------------------------------------
extern "C" void kernel_launch(void* const* d_in, const int* in_sizes, int n_in,
                              void* d_out, int out_size) {
    const float* energies = (const float*)d_in[0];   // (B, 1)
    const float* pv       = (const float*)d_in[1];   // (B, P)
    const float* pt       = (const float*)d_in[2];   // (P,)
    float* out            = (float*)d_out;

    int B = in_sizes[0];
    int P = in_sizes[2];
    if (B > MAXB) B = MAXB;

    int pthreads = (P == 16) ? B * 4 : B;
    int pb = (pthreads + 255) / 256;
    prep_kernel<<<pb, 256>>>(energies, pv, pt, B, P);

    int T  = (B + TILE - 1) / TILE;
    int nb = T * (T + 1) / 2;
    pair_kernel<<<nb, TILE>>>(B, T);

    double cnt = (double)B * (double)(B - 1) * 0.5;
    if (cnt < 1.0) cnt = 1.0;
    final_kernel<<<1, 1>>>(out, cnt);
}

// round 3
// speedup vs baseline: 1.8485x; 1.0133x over previous
#include <cuda_runtime.h>
#include <math.h>

// Accumulators (no allocations allowed; device globals, zero-initialized).
__device__ double g_sum;          // masked pair-loss sum
__device__ unsigned int g_tick;   // block completion counter (self-wrapping)

constexpr int TILE = 256;

// ---------------------------------------------------------------------------
// Single fused kernel:
//   * triangle-tiled O(B^2/2) pairwise loss with direction-select
//   * distances computed in-block (no prep kernel)
//   * last-finishing block writes the final result (no epilogue kernel)
// For each unordered pair {i,j}: exactly one direction is in the mask
// (d_i<d_j xor d_j<d_i; ties negligible for float32 normal data), so add
// relu over the direction with the smaller d^2. Compare d^2 (sqrt monotone).
// ---------------------------------------------------------------------------
__global__ __launch_bounds__(TILE) void fused_kernel(
    const float* __restrict__ energies,
    const float* __restrict__ pv,
    const float* __restrict__ pt,
    int B, int P, int T, int NB, double invcnt,
    float* __restrict__ out)
{
    // --- triangle decode: block bid -> (ti, tj), ti <= tj ---
    int bid = blockIdx.x;
    float tf = 2.0f * T + 1.0f;
    int ti = (int)floorf((tf - sqrtf(tf * tf - 8.0f * (float)bid)) * 0.5f);
    if (ti < 0) ti = 0;
    if (ti > T - 1) ti = T - 1;
    while (ti > 0 && (ti * T - ti * (ti - 1) / 2) > bid) ti--;
    while (((ti + 1) * T - (ti + 1) * ti / 2) <= bid) ti++;
    int tj = ti + (bid - (ti * T - ti * (ti - 1) / 2));

    __shared__ float2 jt[TILE];

    const float NANF = __int_as_float(0x7FC00000);
    int t = threadIdx.x;

    // --- in-block prep: {d^2, e} for one row ---
    auto row_de = [&](int row) -> float2 {
        if (row >= B) return make_float2(0.0f, NANF);  // NaN energy -> relu()=0
        float s = 0.0f;
        if (P == 16) {
            const float4* pv4 = (const float4*)(pv + (size_t)row * 16);
            const float4* pt4 = (const float4*)pt;
            #pragma unroll
            for (int q = 0; q < 4; q++) {
                float4 v = pv4[q];
                float4 w = pt4[q];
                float a = v.x - w.x, b = v.y - w.y;
                float c = v.z - w.z, d = v.w - w.w;
                s = fmaf(a, a, fmaf(b, b, fmaf(c, c, fmaf(d, d, s))));
            }
        } else {
            for (int p = 0; p < P; p++) {
                float df = pv[(size_t)row * P + p] - pt[p];
                s = fmaf(df, df, s);
            }
        }
        return make_float2(s, energies[row]);
    };

    float2 myi = row_de(ti * TILE + t);              // my i row (registers)
    jt[t] = (ti == tj) ? myi : row_de(tj * TILE + t); // j tile (shared)

    float di = myi.x;
    float ai = myi.y + 1.0f;   // e_i + 1  (dir i<j: ai - e_j)
    float bi = 1.0f - myi.y;   // 1 - e_i  (dir j<i: bi + e_j)
    // invalid i row: energy is NaN -> ai, bi NaN -> relu -> 0 (fmaxf semantics)

    __syncthreads();

    float acc0 = 0.0f, acc1 = 0.0f;

    if (ti != tj) {
        #pragma unroll 8
        for (int j = 0; j < TILE; j += 2) {
            float2 t0 = jt[j];
            float2 t1 = jt[j + 1];
            float v0 = (di < t0.x) ? (ai - t0.y) : (bi + t0.y);
            float v1 = (di < t1.x) ? (ai - t1.y) : (bi + t1.y);
            acc0 += fmaxf(v0, 0.0f);
            acc1 += fmaxf(v1, 0.0f);
        }
    } else {
        // diagonal tile: only j > i (each unordered pair once)
        #pragma unroll 8
        for (int j = 0; j < TILE; j++) {
            float2 tv = jt[j];
            float v = (di < tv.x) ? (ai - tv.y) : (bi + tv.y);
            float r = fmaxf(v, 0.0f);
            if (j > t) acc0 += r;
        }
    }

    float acc = acc0 + acc1;

    // --- block reduction ---
    #pragma unroll
    for (int o = 16; o > 0; o >>= 1)
        acc += __shfl_down_sync(0xFFFFFFFFu, acc, o);

    __shared__ float ssum[TILE / 32];
    int w = t >> 5, l = t & 31;
    if (l == 0) ssum[w] = acc;
    __syncthreads();

    // --- global accumulation + last-block epilogue ---
    if (t == 0) {
        float a = 0.0f;
        #pragma unroll
        for (int k = 0; k < TILE / 32; k++) a += ssum[k];
        atomicAdd(&g_sum, (double)a);
        __threadfence();
        // atomicInc wraps to 0 when old == NB-1 -> counter self-resets,
        // keeping the kernel graph-replayable.
        unsigned int old = atomicInc(&g_tick, (unsigned int)(NB - 1));
        if (old == (unsigned int)(NB - 1)) {
            unsigned long long bits =
                atomicExch((unsigned long long*)&g_sum, 0ull); // read + reset
            out[0] = (float)(__longlong_as_double(bits) * invcnt);
        }
    }
}

// ---------------------------------------------------------------------------
extern "C" void kernel_launch(void* const* d_in, const int* in_sizes, int n_in,
                              void* d_out, int out_size) {
    const float* energies = (const float*)d_in[0];   // (B, 1)
    const float* pv       = (const float*)d_in[1];   // (B, P)
    const float* pt       = (const float*)d_in[2];   // (P,)
    float* out            = (float*)d_out;

    int B = in_sizes[0];
    int P = in_sizes[2];

    int T  = (B + TILE - 1) / TILE;
    int NB = T * (T + 1) / 2;

    double cnt = (double)B * (double)(B - 1) * 0.5;
    if (cnt < 1.0) cnt = 1.0;

    fused_kernel<<<NB, TILE>>>(energies, pv, pt, B, P, T, NB, 1.0 / cnt, out);
}